// round 2
// baseline (speedup 1.0000x reference)
#include <cuda_runtime.h>

#define FULLMASK 0xFFFFFFFFu

// One warp per row, 128 elements/iteration (float4 per lane).
// Integer prefix via ballot+popc (no shfl scan). Likelihood ratio carried
// multiplicatively inside the lane (exclusive cumprods, FMA pipe only);
// one __logf + one __expf per lane per iteration; one __fdividef per element.
__global__ void __launch_bounds__(128)
bbm_kernel(const float* __restrict__ obs,
           const float* __restrict__ alpha1,
           const float* __restrict__ beta1,
           const float* __restrict__ alpha2,
           const float* __restrict__ beta2,
           const float* __restrict__ mixw,
           float* __restrict__ out,
           int B, int T)
{
    const int wid  = threadIdx.x >> 5;
    const int lane = threadIdx.x & 31;
    const int row  = blockIdx.x * (blockDim.x >> 5) + wid;
    if (row >= B) return;

    const unsigned ltmask = (lane == 0) ? 0u : (FULLMASK >> (32 - lane));

    const float a1c = __ldg(alpha1 + row);
    const float b1c = __ldg(beta1  + row);
    const float a2c = __ldg(alpha2 + row);
    const float b2c = __ldg(beta2  + row);
    const float ab1 = a1c + b1c;
    const float ab2 = a2c + b2c;
    const float w   = __ldg(mixw);
    const float omw = 1.0f - w;

    const float4* __restrict__ orow =
        reinterpret_cast<const float4*>(obs + (size_t)row * (size_t)T);

    const size_t NT = (size_t)B * (size_t)T;
    float* o_a1 = out + (size_t)row * (size_t)T;
    float* o_b1 = o_a1 + NT;
    float* o_a2 = o_b1 + NT;
    float* o_b2 = o_a2 + NT;
    float* o_pm = o_b2 + NT;

    int   s_carry = 0;     // successes before current position
    float D_carry = 0.0f;  // D(t) = clog2 - clog1, log space across iterations

    const int iters = T >> 7;

    // prefetch depth 2
    float4 v0 = orow[lane];
    float4 v1 = (iters > 1) ? orow[32 + lane] : v0;

    for (int it = 0; it < iters; ++it) {
        const float4 v = v0;
        v0 = v1;
        if (it + 2 < iters) v1 = orow[(it + 2) * 32 + lane];

        int b0 = v.x > 0.5f, b1 = v.y > 0.5f, b2 = v.z > 0.5f, b3 = v.w > 0.5f;

        // ---- integer prefix via ballot (no shfl scan) ----
        const unsigned m0 = __ballot_sync(FULLMASK, b0);
        const unsigned m1 = __ballot_sync(FULLMASK, b1);
        const unsigned m2 = __ballot_sync(FULLMASK, b2);
        const unsigned m3 = __ballot_sync(FULLMASK, b3);
        const int s0 = s_carry + __popc(m0 & ltmask) + __popc(m1 & ltmask)
                               + __popc(m2 & ltmask) + __popc(m3 & ltmask);
        const int cntTot = __popc(m0) + __popc(m1) + __popc(m2) + __popc(m3);

        const int t0 = (it << 7) + (lane << 2);
        const float t0f = (float)t0;

        // ---- per-element ratio factors; exclusive cumulative products ----
        // step ratio r_j = ((base2+x)*(ab1+t)) / ((base1+x)*(ab2+t))
        int bj[4] = {b0, b1, b2, b3};
        float sfv[4];                  // s before element j (as float)
        float num[4], den[4];
        int ss = s0;
        #pragma unroll
        for (int j = 0; j < 4; ++j) {
            const float tf = t0f + (float)j;
            const float sf = (float)ss;
            const float ff = tf - sf;          // exact small ints
            sfv[j] = sf;
            const float xv   = bj[j] ? sf  : ff;
            const float c2   = bj[j] ? a2c : b2c;
            const float c1   = bj[j] ? a1c : b1c;
            num[j] = (c2 + xv) * (ab1 + tf);
            den[j] = (c1 + xv) * (ab2 + tf);
            ss += bj[j];
        }
        // exclusive products (cnex[0]=1) + inclusive totals
        float cnex[4], cdex[4];
        cnex[0] = 1.0f;            cdex[0] = 1.0f;
        cnex[1] = num[0];          cdex[1] = den[0];
        cnex[2] = cnex[1]*num[1];  cdex[2] = cdex[1]*den[1];
        cnex[3] = cnex[2]*num[2];  cdex[3] = cdex[2]*den[2];
        const float cnInc = cnex[3]*num[3];
        const float cdInc = cdex[3]*den[3];

        // one log per lane: this lane's total delta-D
        const float dacc = __logf(__fdividef(cnInc, cdInc));

        // ---- float shfl scan of per-lane deltas ----
        float finc = dacc;
        #pragma unroll
        for (int d = 1; d < 32; d <<= 1) {
            float n = __shfl_up_sync(FULLMASK, finc, d);
            if (lane >= d) finc += n;
        }
        const float Dbase = D_carry + (finc - dacc);   // exclusive prefix
        const float Dtot  = __shfl_sync(FULLMASK, finc, 31);

        // one exp per lane
        const float omwEb = omw * __expf(Dbase);

        // ---- outputs: 1 div per element ----
        float oa1[4], ob1[4], oa2[4], ob2[4], opm[4];
        #pragma unroll
        for (int j = 0; j < 4; ++j) {
            const float tf = t0f + (float)j;
            const float sf = sfv[j];
            const float ff = tf - sf;
            oa1[j] = a1c + sf;
            ob1[j] = b1c + ff;
            oa2[j] = a2c + sf;
            ob2[j] = b2c + ff;
            const float wn = w * cdex[j];
            opm[j] = __fdividef(wn, fmaf(omwEb, cnex[j], wn));
        }

        *reinterpret_cast<float4*>(o_a1 + t0) = make_float4(oa1[0], oa1[1], oa1[2], oa1[3]);
        *reinterpret_cast<float4*>(o_b1 + t0) = make_float4(ob1[0], ob1[1], ob1[2], ob1[3]);
        *reinterpret_cast<float4*>(o_a2 + t0) = make_float4(oa2[0], oa2[1], oa2[2], oa2[3]);
        *reinterpret_cast<float4*>(o_b2 + t0) = make_float4(ob2[0], ob2[1], ob2[2], ob2[3]);
        *reinterpret_cast<float4*>(o_pm + t0) = make_float4(opm[0], opm[1], opm[2], opm[3]);

        s_carry += cntTot;
        D_carry += Dtot;
    }
}

extern "C" void kernel_launch(void* const* d_in, const int* in_sizes, int n_in,
                              void* d_out, int out_size)
{
    const float* obs = (const float*)d_in[0];
    const float* a1  = (const float*)d_in[1];
    const float* b1  = (const float*)d_in[2];
    const float* a2  = (const float*)d_in[3];
    const float* b2  = (const float*)d_in[4];
    const float* mw  = (const float*)d_in[5];

    const int B = in_sizes[1];
    const int T = in_sizes[0] / B;

    const int warpsPerBlock = 4;
    dim3 block(32 * warpsPerBlock);
    dim3 grid((B + warpsPerBlock - 1) / warpsPerBlock);
    bbm_kernel<<<grid, block>>>(obs, a1, b1, a2, b2, mw, (float*)d_out, B, T);
}

// round 3
// speedup vs baseline: 1.1737x; 1.1737x over previous
#include <cuda_runtime.h>

#define FULLMASK 0xFFFFFFFFu
#define WARPS_PER_ROW 8

// One 256-thread block per row. Each warp owns a 1/8 chunk of the row.
// Phase 1: read chunk, pack obs bits into one register/lane, count.
// Block scan of counts -> s_start per chunk; D_base per chunk via lgammaf
// closed form (betaln telescoped) -> no sequential dependence across chunks.
// Phase 2: per-chunk local recurrence (8 sub-iterations of 128 elements),
// bits replayed from registers (obs read exactly once).
__global__ void __launch_bounds__(32 * WARPS_PER_ROW)
bbm_kernel(const float* __restrict__ obs,
           const float* __restrict__ alpha1,
           const float* __restrict__ beta1,
           const float* __restrict__ alpha2,
           const float* __restrict__ beta2,
           const float* __restrict__ mixw,
           float* __restrict__ out,
           int B, int T)
{
    const int wid  = threadIdx.x >> 5;
    const int lane = threadIdx.x & 31;
    const int row  = blockIdx.x;

    const unsigned ltmask = (lane == 0) ? 0u : (FULLMASK >> (32 - lane));

    const float a1c = __ldg(alpha1 + row);
    const float b1c = __ldg(beta1  + row);
    const float a2c = __ldg(alpha2 + row);
    const float b2c = __ldg(beta2  + row);
    const float ab1 = a1c + b1c;
    const float ab2 = a2c + b2c;
    const float w   = __ldg(mixw);
    const float omw = 1.0f - w;

    const int chunk    = T / WARPS_PER_ROW;   // 1024
    const int subiters = chunk >> 7;          // 8 (128 elems / sub-iter)

    const float4* __restrict__ orow =
        reinterpret_cast<const float4*>(obs + (size_t)row * (size_t)T);

    const size_t NT = (size_t)B * (size_t)T;
    float* o_a1 = out + (size_t)row * (size_t)T;
    float* o_b1 = o_a1 + NT;
    float* o_a2 = o_b1 + NT;
    float* o_b2 = o_a2 + NT;
    float* o_pm = o_b2 + NT;

    __shared__ int smem_cnt[WARPS_PER_ROW];

    // ---------- Phase 1: load chunk, pack bits, count ----------
    // sub-iter i of warp wid covers t = wid*chunk + i*128 + lane*4 .. +3
    unsigned packed = 0;
    const int vbase = wid * (chunk >> 2) + lane;   // float4 index base
    #pragma unroll
    for (int i = 0; i < 8; ++i) {
        const float4 v = orow[vbase + i * 32];
        unsigned nib = (unsigned)(v.x > 0.5f)
                     | ((unsigned)(v.y > 0.5f) << 1)
                     | ((unsigned)(v.z > 0.5f) << 2)
                     | ((unsigned)(v.w > 0.5f) << 3);
        packed |= nib << (4 * i);
    }
    const int mycnt = __popc(packed);
    const int warpcnt = __reduce_add_sync(FULLMASK, mycnt);
    if (lane == 0) smem_cnt[wid] = warpcnt;
    __syncthreads();

    int s_start = 0;
    #pragma unroll
    for (int k = 0; k < WARPS_PER_ROW; ++k)
        if (k < wid) s_start += smem_cnt[k];

    // ---------- D_base for this chunk via lgamma closed form ----------
    // D(s,t) = [lgG(a2+s)+lgG(b2+f)-lgG(ab2+t)] - [lgG(a1+s)+lgG(b1+f)-lgG(ab1+t)] - D0
    float D_carry = 0.0f;
    if (wid != 0) {
        const float tf = (float)(wid * chunk);
        const float sf = (float)s_start;
        const float ff = tf - sf;
        const float d2 = (lgammaf(a2c + sf) + lgammaf(b2c + ff) - lgammaf(ab2 + tf))
                       - (lgammaf(a2c) + lgammaf(b2c) - lgammaf(ab2));
        const float d1 = (lgammaf(a1c + sf) + lgammaf(b1c + ff) - lgammaf(ab1 + tf))
                       - (lgammaf(a1c) + lgammaf(b1c) - lgammaf(ab1));
        D_carry = d2 - d1;
    }
    int s_carry = s_start;

    // ---------- Phase 2: local recurrence over 8 sub-iterations ----------
    for (int it = 0; it < subiters; ++it) {
        const unsigned nib = (packed >> (4 * it)) & 0xF;
        const int b0 = (nib)      & 1;
        const int b1 = (nib >> 1) & 1;
        const int b2 = (nib >> 2) & 1;
        const int b3 = (nib >> 3) & 1;

        const unsigned m0 = __ballot_sync(FULLMASK, b0);
        const unsigned m1 = __ballot_sync(FULLMASK, b1);
        const unsigned m2 = __ballot_sync(FULLMASK, b2);
        const unsigned m3 = __ballot_sync(FULLMASK, b3);
        const int s0 = s_carry + __popc(m0 & ltmask) + __popc(m1 & ltmask)
                               + __popc(m2 & ltmask) + __popc(m3 & ltmask);
        const int cntTot = __popc(m0) + __popc(m1) + __popc(m2) + __popc(m3);

        const int   t0  = wid * chunk + (it << 7) + (lane << 2);
        const float t0f = (float)t0;

        // per-element ratio factors; exclusive cumulative products
        int bj[4] = {b0, b1, b2, b3};
        float sfv[4], num[4], den[4];
        int ss = s0;
        #pragma unroll
        for (int j = 0; j < 4; ++j) {
            const float tf = t0f + (float)j;
            const float sf = (float)ss;
            const float ff = tf - sf;
            sfv[j] = sf;
            const float xv = bj[j] ? sf  : ff;
            const float c2 = bj[j] ? a2c : b2c;
            const float c1 = bj[j] ? a1c : b1c;
            num[j] = (c2 + xv) * (ab1 + tf);
            den[j] = (c1 + xv) * (ab2 + tf);
            ss += bj[j];
        }
        float cnex[4], cdex[4];
        cnex[0] = 1.0f;             cdex[0] = 1.0f;
        cnex[1] = num[0];           cdex[1] = den[0];
        cnex[2] = cnex[1] * num[1]; cdex[2] = cdex[1] * den[1];
        cnex[3] = cnex[2] * num[2]; cdex[3] = cdex[2] * den[2];
        const float cnInc = cnex[3] * num[3];
        const float cdInc = cdex[3] * den[3];

        const float dacc = __logf(__fdividef(cnInc, cdInc));

        float finc = dacc;
        #pragma unroll
        for (int d = 1; d < 32; d <<= 1) {
            float n = __shfl_up_sync(FULLMASK, finc, d);
            if (lane >= d) finc += n;
        }
        const float Dbase = D_carry + (finc - dacc);
        const float Dtot  = __shfl_sync(FULLMASK, finc, 31);

        const float omwEb = omw * __expf(Dbase);

        float oa1[4], ob1[4], oa2[4], ob2[4], opm[4];
        #pragma unroll
        for (int j = 0; j < 4; ++j) {
            const float tf = t0f + (float)j;
            const float sf = sfv[j];
            const float ff = tf - sf;
            oa1[j] = a1c + sf;
            ob1[j] = b1c + ff;
            oa2[j] = a2c + sf;
            ob2[j] = b2c + ff;
            const float wn = w * cdex[j];
            opm[j] = __fdividef(wn, fmaf(omwEb, cnex[j], wn));
        }

        *reinterpret_cast<float4*>(o_a1 + t0) = make_float4(oa1[0], oa1[1], oa1[2], oa1[3]);
        *reinterpret_cast<float4*>(o_b1 + t0) = make_float4(ob1[0], ob1[1], ob1[2], ob1[3]);
        *reinterpret_cast<float4*>(o_a2 + t0) = make_float4(oa2[0], oa2[1], oa2[2], oa2[3]);
        *reinterpret_cast<float4*>(o_b2 + t0) = make_float4(ob2[0], ob2[1], ob2[2], ob2[3]);
        *reinterpret_cast<float4*>(o_pm + t0) = make_float4(opm[0], opm[1], opm[2], opm[3]);

        s_carry += cntTot;
        D_carry += Dtot;
    }
}

extern "C" void kernel_launch(void* const* d_in, const int* in_sizes, int n_in,
                              void* d_out, int out_size)
{
    const float* obs = (const float*)d_in[0];
    const float* a1  = (const float*)d_in[1];
    const float* b1  = (const float*)d_in[2];
    const float* a2  = (const float*)d_in[3];
    const float* b2  = (const float*)d_in[4];
    const float* mw  = (const float*)d_in[5];

    const int B = in_sizes[1];
    const int T = in_sizes[0] / B;

    dim3 block(32 * WARPS_PER_ROW);
    dim3 grid(B);
    bbm_kernel<<<grid, block>>>(obs, a1, b1, a2, b2, mw, (float*)d_out, B, T);
}